// round 3
// baseline (speedup 1.0000x reference)
#include <cuda_runtime.h>
#include <cuda_fp16.h>
#include <stdint.h>

#define NN 50000
#define EE 1600000
#define YS1 4224          // padded y stride (halves) for 64->64 layers (33*128)
#define YS3 256           // y stride for layer3
#define YS0 2080          // y stride for layer0 (64*32 + 32)

// ---------------- device scratch (no runtime allocation allowed) ------------
__device__ __align__(16) __half g_y[(size_t)NN * YS1];   // 422 MB
__device__ __align__(16) float g_ans0[NN * 64];
__device__ __align__(16) float g_ans1[NN * 64];
__device__ __align__(16) float g_ans2[NN * 64];
__device__ int    g_cnt[NN + 1];
__device__ int    g_rowp[NN + 1];
__device__ int    g_cursor[NN];
__device__ int    g_sjk[EE];                 // j | (kb<<20)
__device__ __align__(16) float4 g_sw[EE];    // 4 hat-product weights

// ---------------- f32x2 helpers ---------------------------------------------
__device__ __forceinline__ unsigned long long pack2(float x, float y) {
    unsigned long long r;
    asm("mov.b64 %0, {%1, %2};" : "=l"(r) : "f"(x), "f"(y));
    return r;
}
__device__ __forceinline__ void ffma2(unsigned long long& d,
                                      unsigned long long a, unsigned long long b) {
    asm("fma.rn.f32x2 %0, %1, %2, %0;" : "+l"(d) : "l"(a), "l"(b));
}
__device__ __forceinline__ float2 unpack2(unsigned long long v) {
    float lo, hi;
    asm("mov.b64 {%0, %1}, %2;" : "=f"(lo), "=f"(hi) : "l"(v));
    return make_float2(lo, hi);
}

// ---------------- edge preprocessing ----------------------------------------
__global__ void zero_cnt_kernel() {
    int t = blockIdx.x * blockDim.x + threadIdx.x;
    if (t <= NN) g_cnt[t] = 0;
}

__global__ void hist_kernel(const int* __restrict__ ei, int E) {
    int e = blockIdx.x * blockDim.x + threadIdx.x;
    if (e < E) atomicAdd(&g_cnt[ei[e]], 1);
}

__global__ void scan_kernel() {
    __shared__ int sh[1024];
    __shared__ int carry;
    int tid = threadIdx.x;
    if (tid == 0) carry = 0;
    __syncthreads();
    for (int base = 0; base < NN; base += 1024) {
        int idx = base + tid;
        int v = (idx < NN) ? g_cnt[idx] : 0;
        int orig = v;
        sh[tid] = v;
        __syncthreads();
        for (int off = 1; off < 1024; off <<= 1) {
            int t = (tid >= off) ? sh[tid - off] : 0;
            __syncthreads();
            sh[tid] += t;
            __syncthreads();
        }
        int excl = carry + sh[tid] - orig;
        if (idx < NN) { g_rowp[idx] = excl; g_cursor[idx] = excl; }
        int tot = sh[1023];
        __syncthreads();
        if (tid == 0) carry += tot;
        __syncthreads();
    }
    if (tid == 0) g_rowp[NN] = carry;
}

__global__ void scatter_kernel(const float* __restrict__ pos,
                               const int* __restrict__ ei,
                               const int* __restrict__ ej, int E) {
    int e = blockIdx.x * blockDim.x + threadIdx.x;
    if (e >= E) return;
    int i = ei[e], j = ej[e];
    float dx = pos[2 * i]     - pos[2 * j];
    float dy = pos[2 * i + 1] - pos[2 * j + 1];
    dx = fminf(1.f, fmaxf(-1.f, dx));
    dy = fminf(1.f, fmaxf(-1.f, dy));
    float m = (i != j) ? 1.f : 0.f;
    float r = sqrtf(dx * dx + dy * dy + 1e-12f);
    float u = fminf(1.f, fmaxf(-1.f, 2.f * r - 1.f));
    float v = atan2f(dy, dx) * 0.318309886183790672f;   // 1/pi
    float su = (u + 1.f) * 3.5f;
    int   iu = min(6, (int)floorf(su));
    float tu = su - (float)iu;
    float sv = (v + 1.f) * 3.5f;
    int   iv = min(6, (int)floorf(sv));
    float tv = sv - (float)iv;
    float4 w = make_float4((1.f - tu) * (1.f - tv) * m,
                           (1.f - tu) * tv * m,
                           tu * (1.f - tv) * m,
                           tu * tv * m);
    int kb = iu * 8 + iv;
    int p = atomicAdd(&g_cursor[i], 1);
    g_sjk[p] = j | (kb << 20);
    g_sw[p] = w;
}

// ---------------- layer 0 GEMM: y0[j, col] = sum_c X[j,c] * W0(c,col) -------
__global__ void gemm0_kernel(const float* __restrict__ X,
                             const float* __restrict__ cw0,
                             const float* __restrict__ fw0) {
    int idx = blockIdx.x * blockDim.x + threadIdx.x;   // over NN*520
    if (idx >= NN * 520) return;
    int j = idx / 520;
    int c4 = idx - j * 520;
    int col = c4 * 4;
    float4 x = *(const float4*)(X + (size_t)j * 4);
    float ax = 0.f, ay = 0.f, az = 0.f, aw = 0.f;
    const float xs[4] = {x.x, x.y, x.z, x.w};
    #pragma unroll
    for (int c = 0; c < 4; c++) {
        float4 wv;
        if (col < 2048) {
            int k = col >> 5, co = col & 31;
            wv = __ldg((const float4*)(cw0 + (size_t)(k * 4 + c) * 32 + co));
        } else {
            wv = __ldg((const float4*)(fw0 + (size_t)c * 32 + (col - 2048)));
        }
        ax += xs[c] * wv.x; ay += xs[c] * wv.y;
        az += xs[c] * wv.z; aw += xs[c] * wv.w;
    }
    __half2 h0 = __floats2half2_rn(ax, ay);
    __half2 h1 = __floats2half2_rn(az, aw);
    uint2 pkt;
    pkt.x = *(unsigned int*)&h0;
    pkt.y = *(unsigned int*)&h1;
    *(uint2*)(g_y + (size_t)j * YS0 + col) = pkt;
}

// ---------------- layer 0 gather: ans0 = [lin0 | conv0] ---------------------
__global__ void gather0_kernel(const float* __restrict__ cb0,
                               const float* __restrict__ fb0) {
    int warpId = (blockIdx.x * blockDim.x + threadIdx.x) >> 5;
    int lane = threadIdx.x & 31;
    if (warpId >= NN) return;
    int i = warpId;
    int e0 = g_rowp[i], e1 = g_rowp[i + 1];
    float acc = 0.f;
    for (int e = e0; e < e1; e++) {
        int jk = g_sjk[e];
        float4 w = g_sw[e];
        int j = jk & 0xFFFFF;
        int kb = jk >> 20;
        const __half* r = g_y + (size_t)j * YS0 + kb * 32 + lane;
        acc += w.x * __half2float(__ldg(r))
             + w.y * __half2float(__ldg(r + 32))
             + w.z * __half2float(__ldg(r + 256))
             + w.w * __half2float(__ldg(r + 288));
    }
    float lin = __half2float(g_y[(size_t)i * YS0 + 2048 + lane]) + fb0[lane];
    g_ans0[(size_t)i * 64 + lane]      = lin;
    g_ans0[(size_t)i * 64 + 32 + lane] = acc + cb0[lane];
}

// ---------------- main GEMM: Y = relu(A) @ Wcat  (Kdim = 64) ----------------
__global__ void __launch_bounds__(256, 2)
gemm64_kernel(const float* __restrict__ A,
              const float* __restrict__ CW,
              const float* __restrict__ FW,
              int ncols, int ystride, int coutShift, int coutMask) {
    extern __shared__ float sm[];
    float* As = sm;               // [64][128] k-major
    float* Bs = sm + 64 * 128;    // [64][128]
    int n0 = blockIdx.x * 128;
    int m0 = blockIdx.y * 128;
    int tid = threadIdx.x;
    int cout = 1 << coutShift;
    int kcoutTot = 64 << coutShift;

    // A tile: 128 rows x 64 k, transposed into As[k][m], relu applied
    for (int idx = tid; idx < 128 * 16; idx += 256) {
        int k4 = idx >> 7;        // 0..15
        int rr = idx & 127;       // 0..127
        int row = m0 + rr;
        float4 v = make_float4(0.f, 0.f, 0.f, 0.f);
        if (row < NN) v = *(const float4*)(A + (size_t)row * 64 + k4 * 4);
        As[(4 * k4 + 0) * 128 + rr] = fmaxf(v.x, 0.f);
        As[(4 * k4 + 1) * 128 + rr] = fmaxf(v.y, 0.f);
        As[(4 * k4 + 2) * 128 + rr] = fmaxf(v.z, 0.f);
        As[(4 * k4 + 3) * 128 + rr] = fmaxf(v.w, 0.f);
    }
    // B tile: 64 k x 128 cols, gathered from weight layout
    for (int idx = tid; idx < 64 * 128; idx += 256) {
        int k = idx >> 7;
        int cn = idx & 127;
        int col = n0 + cn;
        float w = 0.f;
        if (col < ncols) {
            if (col < kcoutTot) {
                int kk = col >> coutShift;
                int co = col & coutMask;
                w = __ldg(CW + (size_t)(kk * 64 + k) * cout + co);
            } else {
                w = __ldg(FW + (size_t)k * cout + (col - kcoutTot));
            }
        }
        Bs[k * 128 + cn] = w;
    }
    __syncthreads();

    int tx = tid & 15, ty = tid >> 4;  // 16 x 16 threads, 8x8 outputs each
    unsigned long long acc[8][4];
    #pragma unroll
    for (int m = 0; m < 8; m++)
        #pragma unroll
        for (int p = 0; p < 4; p++) acc[m][p] = 0ull;

    const float* ap = As + ty * 8;
    const float* bp = Bs + tx * 8;
    #pragma unroll 8
    for (int k = 0; k < 64; k++) {
        float4 a0 = *(const float4*)(ap + k * 128);
        float4 a1 = *(const float4*)(ap + k * 128 + 4);
        float4 b0 = *(const float4*)(bp + k * 128);
        float4 b1 = *(const float4*)(bp + k * 128 + 4);
        unsigned long long bq0 = pack2(b0.x, b0.y);
        unsigned long long bq1 = pack2(b0.z, b0.w);
        unsigned long long bq2 = pack2(b1.x, b1.y);
        unsigned long long bq3 = pack2(b1.z, b1.w);
        float am[8] = {a0.x, a0.y, a0.z, a0.w, a1.x, a1.y, a1.z, a1.w};
        #pragma unroll
        for (int m = 0; m < 8; m++) {
            unsigned long long ad = pack2(am[m], am[m]);
            ffma2(acc[m][0], ad, bq0);
            ffma2(acc[m][1], ad, bq1);
            ffma2(acc[m][2], ad, bq2);
            ffma2(acc[m][3], ad, bq3);
        }
    }
    // store fp16 (row stride padded to grid width; no column guard needed)
    #pragma unroll
    for (int m = 0; m < 8; m++) {
        int row = m0 + ty * 8 + m;
        if (row < NN) {
            float2 r0 = unpack2(acc[m][0]);
            float2 r1 = unpack2(acc[m][1]);
            float2 r2 = unpack2(acc[m][2]);
            float2 r3 = unpack2(acc[m][3]);
            __half2 h0 = __floats2half2_rn(r0.x, r0.y);
            __half2 h1 = __floats2half2_rn(r1.x, r1.y);
            __half2 h2 = __floats2half2_rn(r2.x, r2.y);
            __half2 h3 = __floats2half2_rn(r3.x, r3.y);
            uint4 pkt;
            pkt.x = *(unsigned int*)&h0;
            pkt.y = *(unsigned int*)&h1;
            pkt.z = *(unsigned int*)&h2;
            pkt.w = *(unsigned int*)&h3;
            *(uint4*)(g_y + (size_t)row * ystride + n0 + tx * 8) = pkt;
        }
    }
}

// ---------------- gather for 64-wide layers (half2, all 64 ch per warp) -----
template <bool RES>
__global__ void gather64_kernel(const float* __restrict__ cb,
                                const float* __restrict__ fb,
                                const float* __restrict__ resid,
                                float* __restrict__ out) {
    int warpId = (blockIdx.x * blockDim.x + threadIdx.x) >> 5;
    int lane = threadIdx.x & 31;
    if (warpId >= NN) return;
    int i = warpId;
    int e0 = g_rowp[i], e1 = g_rowp[i + 1];
    float2 acc = make_float2(0.f, 0.f);
    #pragma unroll 2
    for (int e = e0; e < e1; e++) {
        int jk = g_sjk[e];
        float4 w = g_sw[e];
        int j = jk & 0xFFFFF;
        int kb = jk >> 20;
        const __half2* r = (const __half2*)(g_y + (size_t)j * YS1 + kb * 64 + 2 * lane);
        float2 f0 = __half22float2(__ldg(r));
        float2 f1 = __half22float2(__ldg(r + 32));    // +64 halves
        float2 f2 = __half22float2(__ldg(r + 256));   // +512 halves
        float2 f3 = __half22float2(__ldg(r + 288));   // +576 halves
        acc.x += w.x * f0.x + w.y * f1.x + w.z * f2.x + w.w * f3.x;
        acc.y += w.x * f0.y + w.y * f1.y + w.z * f2.y + w.w * f3.y;
    }
    float2 s = __half22float2(*(const __half2*)(g_y + (size_t)i * YS1 + 4096 + 2 * lane));
    float2 cbv = *(const float2*)(cb + 2 * lane);
    float2 fbv = *(const float2*)(fb + 2 * lane);
    float2 o = make_float2(acc.x + s.x + cbv.x + fbv.x,
                           acc.y + s.y + cbv.y + fbv.y);
    if (RES) {
        float2 rv = *(const float2*)(resid + (size_t)i * 64 + 2 * lane);
        o.x += rv.x; o.y += rv.y;
    }
    *(float2*)(out + (size_t)i * 64 + 2 * lane) = o;
}

// ---------------- final gather (Cout = 2) + /128 ----------------------------
__global__ void gatherF_kernel(const float* __restrict__ cb3,
                               const float* __restrict__ fb3,
                               float* __restrict__ out) {
    int warpId = (blockIdx.x * blockDim.x + threadIdx.x) >> 5;
    int lane = threadIdx.x & 31;
    if (warpId >= NN) return;
    int i = warpId;
    int e0 = g_rowp[i], e1 = g_rowp[i + 1];
    float accx = 0.f, accy = 0.f;
    for (int e = e0 + lane; e < e1; e += 32) {
        int jk = g_sjk[e];
        float4 w = g_sw[e];
        int j = jk & 0xFFFFF;
        int kb = jk >> 20;
        const __half2* r = (const __half2*)(g_y + (size_t)j * YS3 + kb * 2);
        float2 f0 = __half22float2(__ldg(r));       // k=kb  : (co0, co1)
        float2 f1 = __half22float2(__ldg(r + 1));   // k=kb+1
        float2 f2 = __half22float2(__ldg(r + 8));   // k=kb+8
        float2 f3 = __half22float2(__ldg(r + 9));   // k=kb+9
        accx += w.x * f0.x + w.y * f1.x + w.z * f2.x + w.w * f3.x;
        accy += w.x * f0.y + w.y * f1.y + w.z * f2.y + w.w * f3.y;
    }
    #pragma unroll
    for (int off = 16; off > 0; off >>= 1) {
        accx += __shfl_down_sync(0xFFFFFFFFu, accx, off);
        accy += __shfl_down_sync(0xFFFFFFFFu, accy, off);
    }
    if (lane == 0) {
        float2 ds = __half22float2(*(const __half2*)(g_y + (size_t)i * YS3 + 128));
        out[2 * i]     = (accx + ds.x + cb3[0] + fb3[0]) * (1.f / 128.f);
        out[2 * i + 1] = (accy + ds.y + cb3[1] + fb3[1]) * (1.f / 128.f);
    }
}

// ---------------- launch ----------------------------------------------------
extern "C" void kernel_launch(void* const* d_in, const int* in_sizes, int n_in,
                              void* d_out, int out_size) {
    const float* pos  = (const float*)d_in[0];
    const float* feat = (const float*)d_in[1];
    const int*   ei   = (const int*)d_in[2];
    const int*   ej   = (const int*)d_in[3];
    const float* cw0 = (const float*)d_in[4];
    const float* cb0 = (const float*)d_in[5];
    const float* fw0 = (const float*)d_in[6];
    const float* fb0 = (const float*)d_in[7];
    const float* cw1 = (const float*)d_in[8];
    const float* cb1 = (const float*)d_in[9];
    const float* fw1 = (const float*)d_in[10];
    const float* fb1 = (const float*)d_in[11];
    const float* cw2 = (const float*)d_in[12];
    const float* cb2 = (const float*)d_in[13];
    const float* fw2 = (const float*)d_in[14];
    const float* fb2 = (const float*)d_in[15];
    const float* cw3 = (const float*)d_in[16];
    const float* cb3 = (const float*)d_in[17];
    const float* fw3 = (const float*)d_in[18];
    const float* fb3 = (const float*)d_in[19];
    float* out = (float*)d_out;
    int E = in_sizes[2];

    cudaFuncSetAttribute(gemm64_kernel,
                         cudaFuncAttributeMaxDynamicSharedMemorySize, 65536);

    float* a0; cudaGetSymbolAddress((void**)&a0, g_ans0);
    float* a1; cudaGetSymbolAddress((void**)&a1, g_ans1);
    float* a2; cudaGetSymbolAddress((void**)&a2, g_ans2);

    // edge counting sort
    zero_cnt_kernel<<<(NN + 256) / 256, 256>>>();
    hist_kernel<<<(E + 255) / 256, 256>>>(ei, E);
    scan_kernel<<<1, 1024>>>();
    scatter_kernel<<<(E + 255) / 256, 256>>>(pos, ei, ej, E);

    // layer 0
    gemm0_kernel<<<(NN * 520 + 255) / 256, 256>>>(feat, cw0, fw0);
    gather0_kernel<<<(NN * 32 + 255) / 256, 256>>>(cb0, fb0);

    // layer 1
    gemm64_kernel<<<dim3(33, 391), 256, 65536>>>(a0, cw1, fw1, 4160, YS1, 6, 63);
    gather64_kernel<false><<<(NN * 32 + 255) / 256, 256>>>(cb1, fb1, nullptr, a1);

    // layer 2 (residual)
    gemm64_kernel<<<dim3(33, 391), 256, 65536>>>(a1, cw2, fw2, 4160, YS1, 6, 63);
    gather64_kernel<true><<<(NN * 32 + 255) / 256, 256>>>(cb2, fb2, a1, a2);

    // layer 3
    gemm64_kernel<<<dim3(2, 391), 256, 65536>>>(a2, cw3, fw3, 130, YS3, 1, 1);
    gatherF_kernel<<<(NN * 32 + 255) / 256, 256>>>(cb3, fb3, out);
}

// round 4
// speedup vs baseline: 1.2734x; 1.2734x over previous
#include <cuda_runtime.h>
#include <cuda_fp16.h>
#include <stdint.h>

#define NN 50000
#define EE 1600000
#define YS1 4224          // padded y stride (halves) for 64->64 layers (33*128)
#define YS3 256           // y stride for layer3
#define YS0 2080          // y stride for layer0 (64*32 + 32)

// ---------------- device scratch (no runtime allocation allowed) ------------
__device__ __align__(16) __half g_y[(size_t)NN * YS1];   // 422 MB
__device__ __align__(16) float g_ans0[NN * 64];
__device__ __align__(16) float g_ans1[NN * 64];
__device__ __align__(16) float g_ans2[NN * 64];
__device__ int    g_cnt[NN + 1];
__device__ int    g_rowp[NN + 1];
__device__ int    g_cursor[NN];
__device__ int    g_sjk[EE];                 // j | (kb<<20)
__device__ __align__(16) float4 g_sw[EE];    // 4 hat-product weights

// ---------------- mma helpers ------------------------------------------------
__device__ __forceinline__ void ldsm4(uint32_t& r0, uint32_t& r1, uint32_t& r2,
                                      uint32_t& r3, uint32_t addr) {
    asm volatile("ldmatrix.sync.aligned.m8n8.x4.shared.b16 {%0,%1,%2,%3}, [%4];"
                 : "=r"(r0), "=r"(r1), "=r"(r2), "=r"(r3) : "r"(addr));
}
__device__ __forceinline__ void ldsm4t(uint32_t& r0, uint32_t& r1, uint32_t& r2,
                                       uint32_t& r3, uint32_t addr) {
    asm volatile("ldmatrix.sync.aligned.m8n8.x4.trans.shared.b16 {%0,%1,%2,%3}, [%4];"
                 : "=r"(r0), "=r"(r1), "=r"(r2), "=r"(r3) : "r"(addr));
}
__device__ __forceinline__ void mma16816(float* c, const uint32_t* a,
                                         uint32_t b0, uint32_t b1) {
    asm volatile(
        "mma.sync.aligned.m16n8k16.row.col.f32.f16.f16.f32 "
        "{%0,%1,%2,%3}, {%4,%5,%6,%7}, {%8,%9}, {%0,%1,%2,%3};"
        : "+f"(c[0]), "+f"(c[1]), "+f"(c[2]), "+f"(c[3])
        : "r"(a[0]), "r"(a[1]), "r"(a[2]), "r"(a[3]), "r"(b0), "r"(b1));
}

// ---------------- edge preprocessing ----------------------------------------
__global__ void zero_cnt_kernel() {
    int t = blockIdx.x * blockDim.x + threadIdx.x;
    if (t <= NN) g_cnt[t] = 0;
}

__global__ void hist_kernel(const int* __restrict__ ei, int E) {
    int e = blockIdx.x * blockDim.x + threadIdx.x;
    if (e < E) atomicAdd(&g_cnt[ei[e]], 1);
}

__global__ void scan_kernel() {
    __shared__ int sh[1024];
    __shared__ int carry;
    int tid = threadIdx.x;
    if (tid == 0) carry = 0;
    __syncthreads();
    for (int base = 0; base < NN; base += 1024) {
        int idx = base + tid;
        int v = (idx < NN) ? g_cnt[idx] : 0;
        int orig = v;
        sh[tid] = v;
        __syncthreads();
        for (int off = 1; off < 1024; off <<= 1) {
            int t = (tid >= off) ? sh[tid - off] : 0;
            __syncthreads();
            sh[tid] += t;
            __syncthreads();
        }
        int excl = carry + sh[tid] - orig;
        if (idx < NN) { g_rowp[idx] = excl; g_cursor[idx] = excl; }
        int tot = sh[1023];
        __syncthreads();
        if (tid == 0) carry += tot;
        __syncthreads();
    }
    if (tid == 0) g_rowp[NN] = carry;
}

__global__ void scatter_kernel(const float* __restrict__ pos,
                               const int* __restrict__ ei,
                               const int* __restrict__ ej, int E) {
    int e = blockIdx.x * blockDim.x + threadIdx.x;
    if (e >= E) return;
    int i = ei[e], j = ej[e];
    float dx = pos[2 * i]     - pos[2 * j];
    float dy = pos[2 * i + 1] - pos[2 * j + 1];
    dx = fminf(1.f, fmaxf(-1.f, dx));
    dy = fminf(1.f, fmaxf(-1.f, dy));
    float m = (i != j) ? 1.f : 0.f;
    float r = sqrtf(dx * dx + dy * dy + 1e-12f);
    float u = fminf(1.f, fmaxf(-1.f, 2.f * r - 1.f));
    float v = atan2f(dy, dx) * 0.318309886183790672f;   // 1/pi
    float su = (u + 1.f) * 3.5f;
    int   iu = min(6, (int)floorf(su));
    float tu = su - (float)iu;
    float sv = (v + 1.f) * 3.5f;
    int   iv = min(6, (int)floorf(sv));
    float tv = sv - (float)iv;
    float4 w = make_float4((1.f - tu) * (1.f - tv) * m,
                           (1.f - tu) * tv * m,
                           tu * (1.f - tv) * m,
                           tu * tv * m);
    int kb = iu * 8 + iv;
    int p = atomicAdd(&g_cursor[i], 1);
    g_sjk[p] = j | (kb << 20);
    g_sw[p] = w;
}

// ---------------- layer 0 GEMM: y0[j, col] = sum_c X[j,c] * W0(c,col) -------
__global__ void gemm0_kernel(const float* __restrict__ X,
                             const float* __restrict__ cw0,
                             const float* __restrict__ fw0) {
    int idx = blockIdx.x * blockDim.x + threadIdx.x;   // over NN*520
    if (idx >= NN * 520) return;
    int j = idx / 520;
    int c4 = idx - j * 520;
    int col = c4 * 4;
    float4 x = *(const float4*)(X + (size_t)j * 4);
    float ax = 0.f, ay = 0.f, az = 0.f, aw = 0.f;
    const float xs[4] = {x.x, x.y, x.z, x.w};
    #pragma unroll
    for (int c = 0; c < 4; c++) {
        float4 wv;
        if (col < 2048) {
            int k = col >> 5, co = col & 31;
            wv = __ldg((const float4*)(cw0 + (size_t)(k * 4 + c) * 32 + co));
        } else {
            wv = __ldg((const float4*)(fw0 + (size_t)c * 32 + (col - 2048)));
        }
        ax += xs[c] * wv.x; ay += xs[c] * wv.y;
        az += xs[c] * wv.z; aw += xs[c] * wv.w;
    }
    __half2 h0 = __floats2half2_rn(ax, ay);
    __half2 h1 = __floats2half2_rn(az, aw);
    uint2 pkt;
    pkt.x = *(unsigned int*)&h0;
    pkt.y = *(unsigned int*)&h1;
    *(uint2*)(g_y + (size_t)j * YS0 + col) = pkt;
}

// ---------------- layer 0 gather: ans0 = [lin0 | conv0] ---------------------
__global__ void gather0_kernel(const float* __restrict__ cb0,
                               const float* __restrict__ fb0) {
    int warpId = (blockIdx.x * blockDim.x + threadIdx.x) >> 5;
    int lane = threadIdx.x & 31;
    if (warpId >= NN) return;
    int i = warpId;
    int e0 = g_rowp[i], e1 = g_rowp[i + 1];
    float acc = 0.f;
    for (int e = e0; e < e1; e++) {
        int jk = g_sjk[e];
        float4 w = g_sw[e];
        int j = jk & 0xFFFFF;
        int kb = jk >> 20;
        const __half* r = g_y + (size_t)j * YS0 + kb * 32 + lane;
        acc += w.x * __half2float(__ldg(r))
             + w.y * __half2float(__ldg(r + 32))
             + w.z * __half2float(__ldg(r + 256))
             + w.w * __half2float(__ldg(r + 288));
    }
    float lin = __half2float(g_y[(size_t)i * YS0 + 2048 + lane]) + fb0[lane];
    g_ans0[(size_t)i * 64 + lane]      = lin;
    g_ans0[(size_t)i * 64 + 32 + lane] = acc + cb0[lane];
}

// ---------------- main GEMM (tensor cores): Y = relu(A) @ Wcat --------------
// Wcat(k, col) = CW[(kk*64 + k)*Cout + co] for col < 64*Cout
//              = FW[k*Cout + (col - 64*Cout)] otherwise
#define AST 72    // As row stride (halves): 144 B = 9*16, conflict-free, 16B-aligned
#define BST 136   // Bs row stride (halves): 272 B = 17*16

__global__ void __launch_bounds__(256, 2)
gemm64_kernel(const float* __restrict__ A,
              const float* __restrict__ CW,
              const float* __restrict__ FW,
              int ncols, int ystride, int coutShift, int coutMask) {
    extern __shared__ __half sm[];
    __half* As = sm;                 // [128][AST]
    __half* Bs = sm + 128 * AST;     // [64][BST]
    int n0 = blockIdx.x * 128;
    int m0 = blockIdx.y * 128;
    int tid = threadIdx.x;
    int cout = 1 << coutShift;
    int kcoutTot = 64 << coutShift;

    // stage A: 128 rows x 64 k, fp32 -> relu -> fp16, row-major [m][k]
    for (int idx = tid; idx < 128 * 16; idx += 256) {
        int k4 = idx >> 7;        // 0..15 (quad of k)
        int rr = idx & 127;       // row in tile
        int row = m0 + rr;
        float4 v = make_float4(0.f, 0.f, 0.f, 0.f);
        if (row < NN) v = *(const float4*)(A + (size_t)row * 64 + k4 * 4);
        __half2 h01 = __floats2half2_rn(fmaxf(v.x, 0.f), fmaxf(v.y, 0.f));
        __half2 h23 = __floats2half2_rn(fmaxf(v.z, 0.f), fmaxf(v.w, 0.f));
        uint2 pkt;
        pkt.x = *(unsigned int*)&h01;
        pkt.y = *(unsigned int*)&h23;
        *(uint2*)(As + rr * AST + k4 * 4) = pkt;
    }
    // stage B: 64 k x 128 cols fp16, row-major [k][n]
    for (int idx = tid; idx < 64 * 128; idx += 256) {
        int k = idx >> 7;
        int cn = idx & 127;
        int col = n0 + cn;
        float w = 0.f;
        if (col < ncols) {
            if (col < kcoutTot) {
                int kk = col >> coutShift;
                int co = col & coutMask;
                w = __ldg(CW + (size_t)(kk * 64 + k) * cout + co);
            } else {
                w = __ldg(FW + (size_t)k * cout + (col - kcoutTot));
            }
        }
        Bs[k * BST + cn] = __float2half(w);
    }
    __syncthreads();

    int warp = tid >> 5, lane = tid & 31;
    int wm = warp & 3;        // m offset = 32*wm
    int wn = warp >> 2;       // n offset = 64*wn
    uint32_t asBase = (uint32_t)__cvta_generic_to_shared(As);
    uint32_t bsBase = (uint32_t)__cvta_generic_to_shared(Bs);

    float c[2][8][4];
    #pragma unroll
    for (int mi = 0; mi < 2; mi++)
        #pragma unroll
        for (int ni = 0; ni < 8; ni++)
            #pragma unroll
            for (int p = 0; p < 4; p++) c[mi][ni][p] = 0.f;

    #pragma unroll
    for (int ks = 0; ks < 4; ks++) {
        int k0 = ks * 16;
        uint32_t a[2][4];
        #pragma unroll
        for (int mi = 0; mi < 2; mi++) {
            int row = wm * 32 + mi * 16 + (lane & 15);
            int col = k0 + ((lane >> 4) << 3);
            ldsm4(a[mi][0], a[mi][1], a[mi][2], a[mi][3],
                  asBase + (row * AST + col) * 2);
        }
        #pragma unroll
        for (int nq = 0; nq < 4; nq++) {
            int row = k0 + (lane & 15);
            int col = wn * 64 + nq * 16 + ((lane >> 4) << 3);
            uint32_t b0, b1, b2, b3;
            ldsm4t(b0, b1, b2, b3, bsBase + (row * BST + col) * 2);
            #pragma unroll
            for (int mi = 0; mi < 2; mi++) {
                mma16816(c[mi][nq * 2 + 0], a[mi], b0, b1);
                mma16816(c[mi][nq * 2 + 1], a[mi], b2, b3);
            }
        }
    }

    // store fp16 to g_y (padded stride; only row guard needed)
    #pragma unroll
    for (int mi = 0; mi < 2; mi++) {
        #pragma unroll
        for (int ni = 0; ni < 8; ni++) {
            int row0 = m0 + wm * 32 + mi * 16 + (lane >> 2);
            int col = n0 + wn * 64 + ni * 8 + 2 * (lane & 3);
            if (row0 < NN) {
                __half2 h = __floats2half2_rn(c[mi][ni][0], c[mi][ni][1]);
                *(__half2*)(g_y + (size_t)row0 * ystride + col) = h;
            }
            int row1 = row0 + 8;
            if (row1 < NN) {
                __half2 h = __floats2half2_rn(c[mi][ni][2], c[mi][ni][3]);
                *(__half2*)(g_y + (size_t)row1 * ystride + col) = h;
            }
        }
    }
}

// ---------------- gather for 64-wide layers (half2, all 64 ch per warp) -----
template <bool RES>
__global__ void gather64_kernel(const float* __restrict__ cb,
                                const float* __restrict__ fb,
                                const float* __restrict__ resid,
                                float* __restrict__ out) {
    int warpId = (blockIdx.x * blockDim.x + threadIdx.x) >> 5;
    int lane = threadIdx.x & 31;
    if (warpId >= NN) return;
    int i = warpId;
    int e0 = g_rowp[i], e1 = g_rowp[i + 1];
    float2 acc = make_float2(0.f, 0.f);
    #pragma unroll 2
    for (int e = e0; e < e1; e++) {
        int jk = g_sjk[e];
        float4 w = g_sw[e];
        int j = jk & 0xFFFFF;
        int kb = jk >> 20;
        const __half2* r = (const __half2*)(g_y + (size_t)j * YS1 + kb * 64 + 2 * lane);
        float2 f0 = __half22float2(__ldg(r));
        float2 f1 = __half22float2(__ldg(r + 32));    // +64 halves
        float2 f2 = __half22float2(__ldg(r + 256));   // +512 halves
        float2 f3 = __half22float2(__ldg(r + 288));   // +576 halves
        acc.x += w.x * f0.x + w.y * f1.x + w.z * f2.x + w.w * f3.x;
        acc.y += w.x * f0.y + w.y * f1.y + w.z * f2.y + w.w * f3.y;
    }
    float2 s = __half22float2(*(const __half2*)(g_y + (size_t)i * YS1 + 4096 + 2 * lane));
    float2 cbv = *(const float2*)(cb + 2 * lane);
    float2 fbv = *(const float2*)(fb + 2 * lane);
    float2 o = make_float2(acc.x + s.x + cbv.x + fbv.x,
                           acc.y + s.y + cbv.y + fbv.y);
    if (RES) {
        float2 rv = *(const float2*)(resid + (size_t)i * 64 + 2 * lane);
        o.x += rv.x; o.y += rv.y;
    }
    *(float2*)(out + (size_t)i * 64 + 2 * lane) = o;
}

// ---------------- final gather (Cout = 2) + /128 ----------------------------
__global__ void gatherF_kernel(const float* __restrict__ cb3,
                               const float* __restrict__ fb3,
                               float* __restrict__ out) {
    int warpId = (blockIdx.x * blockDim.x + threadIdx.x) >> 5;
    int lane = threadIdx.x & 31;
    if (warpId >= NN) return;
    int i = warpId;
    int e0 = g_rowp[i], e1 = g_rowp[i + 1];
    float accx = 0.f, accy = 0.f;
    for (int e = e0 + lane; e < e1; e += 32) {
        int jk = g_sjk[e];
        float4 w = g_sw[e];
        int j = jk & 0xFFFFF;
        int kb = jk >> 20;
        const __half2* r = (const __half2*)(g_y + (size_t)j * YS3 + kb * 2);
        float2 f0 = __half22float2(__ldg(r));       // k=kb  : (co0, co1)
        float2 f1 = __half22float2(__ldg(r + 1));   // k=kb+1
        float2 f2 = __half22float2(__ldg(r + 8));   // k=kb+8
        float2 f3 = __half22float2(__ldg(r + 9));   // k=kb+9
        accx += w.x * f0.x + w.y * f1.x + w.z * f2.x + w.w * f3.x;
        accy += w.x * f0.y + w.y * f1.y + w.z * f2.y + w.w * f3.y;
    }
    #pragma unroll
    for (int off = 16; off > 0; off >>= 1) {
        accx += __shfl_down_sync(0xFFFFFFFFu, accx, off);
        accy += __shfl_down_sync(0xFFFFFFFFu, accy, off);
    }
    if (lane == 0) {
        float2 ds = __half22float2(*(const __half2*)(g_y + (size_t)i * YS3 + 128));
        out[2 * i]     = (accx + ds.x + cb3[0] + fb3[0]) * (1.f / 128.f);
        out[2 * i + 1] = (accy + ds.y + cb3[1] + fb3[1]) * (1.f / 128.f);
    }
}

// ---------------- launch ----------------------------------------------------
extern "C" void kernel_launch(void* const* d_in, const int* in_sizes, int n_in,
                              void* d_out, int out_size) {
    const float* pos  = (const float*)d_in[0];
    const float* feat = (const float*)d_in[1];
    const int*   ei   = (const int*)d_in[2];
    const int*   ej   = (const int*)d_in[3];
    const float* cw0 = (const float*)d_in[4];
    const float* cb0 = (const float*)d_in[5];
    const float* fw0 = (const float*)d_in[6];
    const float* fb0 = (const float*)d_in[7];
    const float* cw1 = (const float*)d_in[8];
    const float* cb1 = (const float*)d_in[9];
    const float* fw1 = (const float*)d_in[10];
    const float* fb1 = (const float*)d_in[11];
    const float* cw2 = (const float*)d_in[12];
    const float* cb2 = (const float*)d_in[13];
    const float* fw2 = (const float*)d_in[14];
    const float* fb2 = (const float*)d_in[15];
    const float* cw3 = (const float*)d_in[16];
    const float* cb3 = (const float*)d_in[17];
    const float* fw3 = (const float*)d_in[18];
    const float* fb3 = (const float*)d_in[19];
    float* out = (float*)d_out;
    int E = in_sizes[2];

    const int SMEM = (128 * AST + 64 * BST) * 2;   // 35840 B
    cudaFuncSetAttribute(gemm64_kernel,
                         cudaFuncAttributeMaxDynamicSharedMemorySize, SMEM);

    float* a0; cudaGetSymbolAddress((void**)&a0, g_ans0);
    float* a1; cudaGetSymbolAddress((void**)&a1, g_ans1);
    float* a2; cudaGetSymbolAddress((void**)&a2, g_ans2);

    // edge counting sort
    zero_cnt_kernel<<<(NN + 256) / 256, 256>>>();
    hist_kernel<<<(E + 255) / 256, 256>>>(ei, E);
    scan_kernel<<<1, 1024>>>();
    scatter_kernel<<<(E + 255) / 256, 256>>>(pos, ei, ej, E);

    // layer 0
    gemm0_kernel<<<(NN * 520 + 255) / 256, 256>>>(feat, cw0, fw0);
    gather0_kernel<<<(NN * 32 + 255) / 256, 256>>>(cb0, fb0);

    // layer 1
    gemm64_kernel<<<dim3(33, 391), 256, SMEM>>>(a0, cw1, fw1, 4160, YS1, 6, 63);
    gather64_kernel<false><<<(NN * 32 + 255) / 256, 256>>>(cb1, fb1, nullptr, a1);

    // layer 2 (residual)
    gemm64_kernel<<<dim3(33, 391), 256, SMEM>>>(a1, cw2, fw2, 4160, YS1, 6, 63);
    gather64_kernel<true><<<(NN * 32 + 255) / 256, 256>>>(cb2, fb2, a1, a2);

    // layer 3
    gemm64_kernel<<<dim3(2, 391), 256, SMEM>>>(a2, cw3, fw3, 130, YS3, 1, 1);
    gatherF_kernel<<<(NN * 32 + 255) / 256, 256>>>(cb3, fb3, out);
}

// round 5
// speedup vs baseline: 2.5513x; 2.0036x over previous
#include <cuda_runtime.h>
#include <cuda_fp16.h>
#include <stdint.h>

#define NN 50000
#define EE 1600000
#define YS1 4224          // padded y stride (halves) for 64->64 layers (33*128)
#define YS3 256           // y stride for layer3
#define YS0 2080          // y stride for layer0 (64*32 + 32)
#define NPAD 4224         // packed-weight column pad
#define SCAN_B 49         // ceil(50000/1024)

// ---------------- device scratch (no runtime allocation allowed) ------------
__device__ __align__(16) __half g_y[(size_t)NN * YS1];   // 422 MB
__device__ __align__(16) __half g_wc[64 * NPAD];         // packed fp16 Wcat
__device__ __align__(16) __half g_ah[NN * 64];           // relu(ans) fp16 (GEMM A)
__device__ __align__(16) float  g_ansF[NN * 64];         // layer1 out fp32 (residual)
__device__ int    g_cnt[NN + 1];
__device__ int    g_rowp[NN + 1];
__device__ int    g_cursor[NN];
__device__ int    g_bsum[SCAN_B];
__device__ int    g_boff[SCAN_B + 1];
__device__ int    g_sjk[EE];                 // j | (kb<<20)
__device__ __align__(16) float4 g_sw[EE];    // 4 hat-product weights

// ---------------- mma helpers ------------------------------------------------
__device__ __forceinline__ void ldsm4(uint32_t& r0, uint32_t& r1, uint32_t& r2,
                                      uint32_t& r3, uint32_t addr) {
    asm volatile("ldmatrix.sync.aligned.m8n8.x4.shared.b16 {%0,%1,%2,%3}, [%4];"
                 : "=r"(r0), "=r"(r1), "=r"(r2), "=r"(r3) : "r"(addr));
}
__device__ __forceinline__ void ldsm4t(uint32_t& r0, uint32_t& r1, uint32_t& r2,
                                       uint32_t& r3, uint32_t addr) {
    asm volatile("ldmatrix.sync.aligned.m8n8.x4.trans.shared.b16 {%0,%1,%2,%3}, [%4];"
                 : "=r"(r0), "=r"(r1), "=r"(r2), "=r"(r3) : "r"(addr));
}
__device__ __forceinline__ void mma16816(float* c, const uint32_t* a,
                                         uint32_t b0, uint32_t b1) {
    asm volatile(
        "mma.sync.aligned.m16n8k16.row.col.f32.f16.f16.f32 "
        "{%0,%1,%2,%3}, {%4,%5,%6,%7}, {%8,%9}, {%0,%1,%2,%3};"
        : "+f"(c[0]), "+f"(c[1]), "+f"(c[2]), "+f"(c[3])
        : "r"(a[0]), "r"(a[1]), "r"(a[2]), "r"(a[3]), "r"(b0), "r"(b1));
}

// ---------------- edge preprocessing ----------------------------------------
__global__ void zero_cnt_kernel() {
    int t = blockIdx.x * blockDim.x + threadIdx.x;
    if (t <= NN) g_cnt[t] = 0;
}

__global__ void hist_kernel(const int* __restrict__ ei, int E) {
    int e = blockIdx.x * blockDim.x + threadIdx.x;
    if (e < E) atomicAdd(&g_cnt[__ldg(ei + e)], 1);
}

// phase 1: per-block sums of g_cnt
__global__ void scan1_kernel() {
    __shared__ int sh[1024];
    int b = blockIdx.x, tid = threadIdx.x;
    int idx = b * 1024 + tid;
    int v = (idx < NN) ? g_cnt[idx] : 0;
    sh[tid] = v;
    __syncthreads();
    for (int off = 512; off > 0; off >>= 1) {
        if (tid < off) sh[tid] += sh[tid + off];
        __syncthreads();
    }
    if (tid == 0) g_bsum[b] = sh[0];
}

// phase 2: scan the SCAN_B block sums
__global__ void scan2_kernel() {
    __shared__ int sh[64];
    int tid = threadIdx.x;
    int v = (tid < SCAN_B) ? g_bsum[tid] : 0;
    sh[tid] = v;
    __syncthreads();
    for (int off = 1; off < 64; off <<= 1) {
        int t = (tid >= off) ? sh[tid - off] : 0;
        __syncthreads();
        sh[tid] += t;
        __syncthreads();
    }
    if (tid < SCAN_B) g_boff[tid] = sh[tid] - v;
    if (tid == SCAN_B - 1) g_boff[SCAN_B] = sh[tid];
}

// phase 3: local scan + block offset -> rowp, cursor
__global__ void scan3_kernel() {
    __shared__ int sh[1024];
    int b = blockIdx.x, tid = threadIdx.x;
    int idx = b * 1024 + tid;
    int v = (idx < NN) ? g_cnt[idx] : 0;
    int orig = v;
    sh[tid] = v;
    __syncthreads();
    for (int off = 1; off < 1024; off <<= 1) {
        int t = (tid >= off) ? sh[tid - off] : 0;
        __syncthreads();
        sh[tid] += t;
        __syncthreads();
    }
    if (idx < NN) {
        int excl = g_boff[b] + sh[tid] - orig;
        g_rowp[idx] = excl;
        g_cursor[idx] = excl;
    }
    if (b == 0 && tid == 0) g_rowp[NN] = g_boff[SCAN_B];
}

__global__ void scatter_kernel(const float* __restrict__ pos,
                               const int* __restrict__ ei,
                               const int* __restrict__ ej, int E) {
    int e = blockIdx.x * blockDim.x + threadIdx.x;
    if (e >= E) return;
    int i = ei[e], j = ej[e];
    float dx = pos[2 * i]     - pos[2 * j];
    float dy = pos[2 * i + 1] - pos[2 * j + 1];
    dx = fminf(1.f, fmaxf(-1.f, dx));
    dy = fminf(1.f, fmaxf(-1.f, dy));
    float m = (i != j) ? 1.f : 0.f;
    float r = sqrtf(dx * dx + dy * dy + 1e-12f);
    float u = fminf(1.f, fmaxf(-1.f, 2.f * r - 1.f));
    float v = atan2f(dy, dx) * 0.318309886183790672f;   // 1/pi
    float su = (u + 1.f) * 3.5f;
    int   iu = min(6, (int)floorf(su));
    float tu = su - (float)iu;
    float sv = (v + 1.f) * 3.5f;
    int   iv = min(6, (int)floorf(sv));
    float tv = sv - (float)iv;
    float4 w = make_float4((1.f - tu) * (1.f - tv) * m,
                           (1.f - tu) * tv * m,
                           tu * (1.f - tv) * m,
                           tu * tv * m);
    int kb = iu * 8 + iv;
    int p = atomicAdd(&g_cursor[i], 1);
    g_sjk[p] = j | (kb << 20);
    g_sw[p] = w;
}

// ---------------- layer 0 GEMM: y0[j, col] = sum_c X[j,c] * W0(c,col) -------
__global__ void gemm0_kernel(const float* __restrict__ X,
                             const float* __restrict__ cw0,
                             const float* __restrict__ fw0) {
    int idx = blockIdx.x * blockDim.x + threadIdx.x;   // over NN*520
    if (idx >= NN * 520) return;
    int j = idx / 520;
    int c4 = idx - j * 520;
    int col = c4 * 4;
    float4 x = *(const float4*)(X + (size_t)j * 4);
    float ax = 0.f, ay = 0.f, az = 0.f, aw = 0.f;
    const float xs[4] = {x.x, x.y, x.z, x.w};
    #pragma unroll
    for (int c = 0; c < 4; c++) {
        float4 wv;
        if (col < 2048) {
            int k = col >> 5, co = col & 31;
            wv = __ldg((const float4*)(cw0 + (size_t)(k * 4 + c) * 32 + co));
        } else {
            wv = __ldg((const float4*)(fw0 + (size_t)c * 32 + (col - 2048)));
        }
        ax += xs[c] * wv.x; ay += xs[c] * wv.y;
        az += xs[c] * wv.z; aw += xs[c] * wv.w;
    }
    __half2 h0 = __floats2half2_rn(ax, ay);
    __half2 h1 = __floats2half2_rn(az, aw);
    uint2 pkt;
    pkt.x = *(unsigned int*)&h0;
    pkt.y = *(unsigned int*)&h1;
    *(uint2*)(g_y + (size_t)j * YS0 + col) = pkt;
}

// ---------------- layer 0 gather: g_ah = relu([lin0 | conv0]) ---------------
__global__ void gather0_kernel(const float* __restrict__ cb0,
                               const float* __restrict__ fb0) {
    int warpId = (blockIdx.x * blockDim.x + threadIdx.x) >> 5;
    int lane = threadIdx.x & 31;
    if (warpId >= NN) return;
    int i = warpId;
    int e0 = g_rowp[i], e1 = g_rowp[i + 1];
    float acc = 0.f;
    #pragma unroll 4
    for (int e = e0; e < e1; e++) {
        int jk = g_sjk[e];
        float4 w = g_sw[e];
        int j = jk & 0xFFFFF;
        int kb = jk >> 20;
        const __half* r = g_y + (size_t)j * YS0 + kb * 32 + lane;
        acc += w.x * __half2float(__ldg(r))
             + w.y * __half2float(__ldg(r + 32))
             + w.z * __half2float(__ldg(r + 256))
             + w.w * __half2float(__ldg(r + 288));
    }
    float lin = __half2float(g_y[(size_t)i * YS0 + 2048 + lane]) + fb0[lane];
    g_ah[(size_t)i * 64 + lane]      = __float2half(fmaxf(lin, 0.f));
    g_ah[(size_t)i * 64 + 32 + lane] = __float2half(fmaxf(acc + cb0[lane], 0.f));
}

// ---------------- weight pack: g_wc[k, col] = fp16 Wcat(k, col) -------------
__global__ void pack_kernel(const float* __restrict__ CW,
                            const float* __restrict__ FW,
                            int ncols, int coutShift, int coutMask) {
    int idx = blockIdx.x * blockDim.x + threadIdx.x;   // over 64*NPAD
    if (idx >= 64 * NPAD) return;
    int k = idx / NPAD;
    int col = idx - k * NPAD;
    int cout = 1 << coutShift;
    int kcoutTot = 64 << coutShift;
    float w = 0.f;
    if (col < ncols) {
        if (col < kcoutTot) {
            int kk = col >> coutShift;
            int co = col & coutMask;
            w = __ldg(CW + (size_t)(kk * 64 + k) * cout + co);
        } else {
            w = __ldg(FW + (size_t)k * cout + (col - kcoutTot));
        }
    }
    g_wc[k * NPAD + col] = __float2half(w);
}

// ---------------- main GEMM (tensor cores): Y = Ah @ Wcat -------------------
#define AST 72    // As row stride (halves): 144 B = 9*16
#define BST 136   // Bs row stride (halves): 272 B = 17*16
#define CST 136   // C staging row stride (halves)
#define SMEMB ((128 * AST + 64 * BST) * 2)   // 35840 B (>= 128*CST*2 = 34816)

__global__ void __launch_bounds__(256, 2)
gemm64_kernel(int ystride) {
    extern __shared__ __half sm[];
    __half* As = sm;                 // [128][AST]
    __half* Bs = sm + 128 * AST;     // [64][BST]
    int n0 = blockIdx.x * 128;
    int m0 = blockIdx.y * 128;
    int tid = threadIdx.x;

    // stage A: vector copy of pre-relu'd fp16 activations
    #pragma unroll
    for (int it = 0; it < 4; it++) {
        int idx = tid + it * 256;         // 1024 uint4 chunks
        int row = idx >> 3;
        int c8 = idx & 7;
        uint4 v = make_uint4(0, 0, 0, 0);
        if (m0 + row < NN)
            v = __ldg((const uint4*)(g_ah + (size_t)(m0 + row) * 64 + c8 * 8));
        *(uint4*)(As + row * AST + c8 * 8) = v;
    }
    // stage B: vector copy of packed weights
    #pragma unroll
    for (int it = 0; it < 4; it++) {
        int idx = tid + it * 256;         // 1024 uint4 chunks
        int row = idx >> 4;
        int c8 = idx & 15;
        uint4 v = __ldg((const uint4*)(g_wc + row * NPAD + n0 + c8 * 8));
        *(uint4*)(Bs + row * BST + c8 * 8) = v;
    }
    __syncthreads();

    int warp = tid >> 5, lane = tid & 31;
    int wm = warp & 3;        // m offset = 32*wm
    int wn = warp >> 2;       // n offset = 64*wn
    uint32_t asBase = (uint32_t)__cvta_generic_to_shared(As);
    uint32_t bsBase = (uint32_t)__cvta_generic_to_shared(Bs);

    float c[2][8][4];
    #pragma unroll
    for (int mi = 0; mi < 2; mi++)
        #pragma unroll
        for (int ni = 0; ni < 8; ni++)
            #pragma unroll
            for (int p = 0; p < 4; p++) c[mi][ni][p] = 0.f;

    #pragma unroll
    for (int ks = 0; ks < 4; ks++) {
        int k0 = ks * 16;
        uint32_t a[2][4];
        #pragma unroll
        for (int mi = 0; mi < 2; mi++) {
            int row = wm * 32 + mi * 16 + (lane & 15);
            int col = k0 + ((lane >> 4) << 3);
            ldsm4(a[mi][0], a[mi][1], a[mi][2], a[mi][3],
                  asBase + (row * AST + col) * 2);
        }
        #pragma unroll
        for (int nq = 0; nq < 4; nq++) {
            int row = k0 + (lane & 15);
            int col = wn * 64 + nq * 16 + ((lane >> 4) << 3);
            uint32_t b0, b1, b2, b3;
            ldsm4t(b0, b1, b2, b3, bsBase + (row * BST + col) * 2);
            #pragma unroll
            for (int mi = 0; mi < 2; mi++) {
                mma16816(c[mi][nq * 2 + 0], a[mi], b0, b1);
                mma16816(c[mi][nq * 2 + 1], a[mi], b2, b3);
            }
        }
    }

    // epilogue: fragments -> smem (fp16) -> coalesced 256B-row global stores
    __syncthreads();                      // everyone done reading As/Bs
    __half* Cs = sm;                      // [128][CST]
    #pragma unroll
    for (int mi = 0; mi < 2; mi++) {
        #pragma unroll
        for (int ni = 0; ni < 8; ni++) {
            int r0 = wm * 32 + mi * 16 + (lane >> 2);
            int col = wn * 64 + ni * 8 + 2 * (lane & 3);
            *(__half2*)(Cs + r0 * CST + col) =
                __floats2half2_rn(c[mi][ni][0], c[mi][ni][1]);
            *(__half2*)(Cs + (r0 + 8) * CST + col) =
                __floats2half2_rn(c[mi][ni][2], c[mi][ni][3]);
        }
    }
    __syncthreads();
    #pragma unroll
    for (int p = 0; p < 4; p++) {
        int row = p * 32 + (tid >> 3);
        int gr = m0 + row;
        if (gr < NN) {
            int col = (tid & 7) * 16;
            uint4 v0 = *(const uint4*)(Cs + row * CST + col);
            uint4 v1 = *(const uint4*)(Cs + row * CST + col + 8);
            __half* dst = g_y + (size_t)gr * ystride + n0 + col;
            *(uint4*)(dst) = v0;
            *(uint4*)(dst + 8) = v1;
        }
    }
}

// ---------------- gather for 64-wide layers (half2, all 64 ch per warp) -----
// RES: add fp32 residual; WF32: also write fp32 ans (needed as next residual)
template <bool RES, bool WF32>
__global__ void gather64_kernel(const float* __restrict__ cb,
                                const float* __restrict__ fb,
                                const float* __restrict__ resid,
                                float* __restrict__ outF) {
    int warpId = (blockIdx.x * blockDim.x + threadIdx.x) >> 5;
    int lane = threadIdx.x & 31;
    if (warpId >= NN) return;
    int i = warpId;
    int e0 = g_rowp[i], e1 = g_rowp[i + 1];
    float2 acc = make_float2(0.f, 0.f);
    #pragma unroll 4
    for (int e = e0; e < e1; e++) {
        int jk = g_sjk[e];
        float4 w = g_sw[e];
        int j = jk & 0xFFFFF;
        int kb = jk >> 20;
        const __half2* r = (const __half2*)(g_y + (size_t)j * YS1 + kb * 64 + 2 * lane);
        float2 f0 = __half22float2(__ldg(r));
        float2 f1 = __half22float2(__ldg(r + 32));    // +64 halves
        float2 f2 = __half22float2(__ldg(r + 256));   // +512 halves
        float2 f3 = __half22float2(__ldg(r + 288));   // +576 halves
        acc.x += w.x * f0.x + w.y * f1.x + w.z * f2.x + w.w * f3.x;
        acc.y += w.x * f0.y + w.y * f1.y + w.z * f2.y + w.w * f3.y;
    }
    float2 s = __half22float2(*(const __half2*)(g_y + (size_t)i * YS1 + 4096 + 2 * lane));
    float2 cbv = *(const float2*)(cb + 2 * lane);
    float2 fbv = *(const float2*)(fb + 2 * lane);
    float2 o = make_float2(acc.x + s.x + cbv.x + fbv.x,
                           acc.y + s.y + cbv.y + fbv.y);
    if (RES) {
        float2 rv = *(const float2*)(resid + (size_t)i * 64 + 2 * lane);
        o.x += rv.x; o.y += rv.y;
    }
    if (WF32)
        *(float2*)(outF + (size_t)i * 64 + 2 * lane) = o;
    *(__half2*)(g_ah + (size_t)i * 64 + 2 * lane) =
        __floats2half2_rn(fmaxf(o.x, 0.f), fmaxf(o.y, 0.f));
}

// ---------------- final gather (Cout = 2) + /128 ----------------------------
__global__ void gatherF_kernel(const float* __restrict__ cb3,
                               const float* __restrict__ fb3,
                               float* __restrict__ out) {
    int warpId = (blockIdx.x * blockDim.x + threadIdx.x) >> 5;
    int lane = threadIdx.x & 31;
    if (warpId >= NN) return;
    int i = warpId;
    int e0 = g_rowp[i], e1 = g_rowp[i + 1];
    float accx = 0.f, accy = 0.f;
    for (int e = e0 + lane; e < e1; e += 32) {
        int jk = g_sjk[e];
        float4 w = g_sw[e];
        int j = jk & 0xFFFFF;
        int kb = jk >> 20;
        const __half2* r = (const __half2*)(g_y + (size_t)j * YS3 + kb * 2);
        float2 f0 = __half22float2(__ldg(r));       // k=kb  : (co0, co1)
        float2 f1 = __half22float2(__ldg(r + 1));   // k=kb+1
        float2 f2 = __half22float2(__ldg(r + 8));   // k=kb+8
        float2 f3 = __half22float2(__ldg(r + 9));   // k=kb+9
        accx += w.x * f0.x + w.y * f1.x + w.z * f2.x + w.w * f3.x;
        accy += w.x * f0.y + w.y * f1.y + w.z * f2.y + w.w * f3.y;
    }
    #pragma unroll
    for (int off = 16; off > 0; off >>= 1) {
        accx += __shfl_down_sync(0xFFFFFFFFu, accx, off);
        accy += __shfl_down_sync(0xFFFFFFFFu, accy, off);
    }
    if (lane == 0) {
        float2 ds = __half22float2(*(const __half2*)(g_y + (size_t)i * YS3 + 128));
        out[2 * i]     = (accx + ds.x + cb3[0] + fb3[0]) * (1.f / 128.f);
        out[2 * i + 1] = (accy + ds.y + cb3[1] + fb3[1]) * (1.f / 128.f);
    }
}

// ---------------- launch ----------------------------------------------------
extern "C" void kernel_launch(void* const* d_in, const int* in_sizes, int n_in,
                              void* d_out, int out_size) {
    const float* pos  = (const float*)d_in[0];
    const float* feat = (const float*)d_in[1];
    const int*   ei   = (const int*)d_in[2];
    const int*   ej   = (const int*)d_in[3];
    const float* cw0 = (const float*)d_in[4];
    const float* cb0 = (const float*)d_in[5];
    const float* fw0 = (const float*)d_in[6];
    const float* fb0 = (const float*)d_in[7];
    const float* cw1 = (const float*)d_in[8];
    const float* cb1 = (const float*)d_in[9];
    const float* fw1 = (const float*)d_in[10];
    const float* fb1 = (const float*)d_in[11];
    const float* cw2 = (const float*)d_in[12];
    const float* cb2 = (const float*)d_in[13];
    const float* fw2 = (const float*)d_in[14];
    const float* fb2 = (const float*)d_in[15];
    const float* cw3 = (const float*)d_in[16];
    const float* cb3 = (const float*)d_in[17];
    const float* fw3 = (const float*)d_in[18];
    const float* fb3 = (const float*)d_in[19];
    float* out = (float*)d_out;
    int E = in_sizes[2];

    cudaFuncSetAttribute(gemm64_kernel,
                         cudaFuncAttributeMaxDynamicSharedMemorySize, SMEMB);

    float* aF; cudaGetSymbolAddress((void**)&aF, g_ansF);

    // edge counting sort
    zero_cnt_kernel<<<(NN + 256) / 256, 256>>>();
    hist_kernel<<<(E + 255) / 256, 256>>>(ei, E);
    scan1_kernel<<<SCAN_B, 1024>>>();
    scan2_kernel<<<1, 64>>>();
    scan3_kernel<<<SCAN_B, 1024>>>();
    scatter_kernel<<<(E + 255) / 256, 256>>>(pos, ei, ej, E);

    // layer 0
    gemm0_kernel<<<(NN * 520 + 255) / 256, 256>>>(feat, cw0, fw0);
    gather0_kernel<<<(NN * 32 + 255) / 256, 256>>>(cb0, fb0);

    // layer 1
    pack_kernel<<<(64 * NPAD + 255) / 256, 256>>>(cw1, fw1, 4160, 6, 63);
    gemm64_kernel<<<dim3(33, 391), 256, SMEMB>>>(YS1);
    gather64_kernel<false, true><<<(NN * 32 + 255) / 256, 256>>>(cb1, fb1, nullptr, aF);

    // layer 2 (residual = ansF)
    pack_kernel<<<(64 * NPAD + 255) / 256, 256>>>(cw2, fw2, 4160, 6, 63);
    gemm64_kernel<<<dim3(33, 391), 256, SMEMB>>>(YS1);
    gather64_kernel<true, false><<<(NN * 32 + 255) / 256, 256>>>(cb2, fb2, aF, nullptr);

    // layer 3
    pack_kernel<<<(64 * NPAD + 255) / 256, 256>>>(cw3, fw3, 130, 1, 1);
    gemm64_kernel<<<dim3(2, 391), 256, SMEMB>>>(YS3);
    gatherF_kernel<<<(NN * 32 + 255) / 256, 256>>>(cb3, fb3, out);
}

// round 6
// speedup vs baseline: 2.5620x; 1.0042x over previous
#include <cuda_runtime.h>
#include <cuda_fp16.h>
#include <stdint.h>

#define NN 50000
#define EE 1600000
#define YS1 4224          // padded y stride (halves) for 64->64 layers (33*128)
#define YS3 256           // y stride for layer3
#define NPAD 4224         // packed-weight column pad (layers 1/2)
#define SCAN_B 49         // ceil(50000/1024)

// ---------------- device scratch (no runtime allocation allowed) ------------
__device__ __align__(16) __half g_y[(size_t)NN * YS1];   // 422 MB
__device__ __align__(16) __half g_wc[64 * NPAD];         // packed fp16 Wcat (layers 1-3)
__device__ __align__(16) __half g_ah[NN * 64];           // relu(ans) fp16 (GEMM A)
__device__ __align__(16) float  g_ansF[NN * 64];         // layer1 out fp32 (residual)
__device__ __align__(16) __half g_m0[(size_t)NN * 320];  // layer0 moments + x, fp16
__device__ __align__(16) __half g_wb0[320 * 64];         // layer0 packed weights
__device__ float  g_bias0[64];
__device__ float  g_bias[64];
__device__ int    g_cnt[NN + 1];
__device__ int    g_rowp[NN + 1];
__device__ int    g_cursor[NN];
__device__ int    g_bsum[SCAN_B];
__device__ int    g_boff[SCAN_B + 1];
__device__ int    g_sjk[EE];                 // j | (kb<<20)
__device__ __align__(16) float4 g_sw[EE];    // 4 hat-product weights

// ---------------- mma helpers ------------------------------------------------
__device__ __forceinline__ void ldsm4(uint32_t& r0, uint32_t& r1, uint32_t& r2,
                                      uint32_t& r3, uint32_t addr) {
    asm volatile("ldmatrix.sync.aligned.m8n8.x4.shared.b16 {%0,%1,%2,%3}, [%4];"
                 : "=r"(r0), "=r"(r1), "=r"(r2), "=r"(r3) : "r"(addr));
}
__device__ __forceinline__ void ldsm4t(uint32_t& r0, uint32_t& r1, uint32_t& r2,
                                       uint32_t& r3, uint32_t addr) {
    asm volatile("ldmatrix.sync.aligned.m8n8.x4.trans.shared.b16 {%0,%1,%2,%3}, [%4];"
                 : "=r"(r0), "=r"(r1), "=r"(r2), "=r"(r3) : "r"(addr));
}
__device__ __forceinline__ void mma16816(float* c, const uint32_t* a,
                                         uint32_t b0, uint32_t b1) {
    asm volatile(
        "mma.sync.aligned.m16n8k16.row.col.f32.f16.f16.f32 "
        "{%0,%1,%2,%3}, {%4,%5,%6,%7}, {%8,%9}, {%0,%1,%2,%3};"
        : "+f"(c[0]), "+f"(c[1]), "+f"(c[2]), "+f"(c[3])
        : "r"(a[0]), "r"(a[1]), "r"(a[2]), "r"(a[3]), "r"(b0), "r"(b1));
}

// ---------------- edge preprocessing ----------------------------------------
__global__ void zero_cnt_kernel() {
    int t = blockIdx.x * blockDim.x + threadIdx.x;
    if (t <= NN) g_cnt[t] = 0;
}

__global__ void hist_kernel(const int* __restrict__ ei, int E) {
    int e = blockIdx.x * blockDim.x + threadIdx.x;
    if (e < E) atomicAdd(&g_cnt[__ldg(ei + e)], 1);
}

__global__ void scan1_kernel() {
    __shared__ int sh[1024];
    int b = blockIdx.x, tid = threadIdx.x;
    int idx = b * 1024 + tid;
    int v = (idx < NN) ? g_cnt[idx] : 0;
    sh[tid] = v;
    __syncthreads();
    for (int off = 512; off > 0; off >>= 1) {
        if (tid < off) sh[tid] += sh[tid + off];
        __syncthreads();
    }
    if (tid == 0) g_bsum[b] = sh[0];
}

__global__ void scan2_kernel() {
    __shared__ int sh[64];
    int tid = threadIdx.x;
    int v = (tid < SCAN_B) ? g_bsum[tid] : 0;
    sh[tid] = v;
    __syncthreads();
    for (int off = 1; off < 64; off <<= 1) {
        int t = (tid >= off) ? sh[tid - off] : 0;
        __syncthreads();
        sh[tid] += t;
        __syncthreads();
    }
    if (tid < SCAN_B) g_boff[tid] = sh[tid] - v;
    if (tid == SCAN_B - 1) g_boff[SCAN_B] = sh[tid];
}

__global__ void scan3_kernel() {
    __shared__ int sh[1024];
    int b = blockIdx.x, tid = threadIdx.x;
    int idx = b * 1024 + tid;
    int v = (idx < NN) ? g_cnt[idx] : 0;
    int orig = v;
    sh[tid] = v;
    __syncthreads();
    for (int off = 1; off < 1024; off <<= 1) {
        int t = (tid >= off) ? sh[tid - off] : 0;
        __syncthreads();
        sh[tid] += t;
        __syncthreads();
    }
    if (idx < NN) {
        int excl = g_boff[b] + sh[tid] - orig;
        g_rowp[idx] = excl;
        g_cursor[idx] = excl;
    }
    if (b == 0 && tid == 0) g_rowp[NN] = g_boff[SCAN_B];
}

__global__ void scatter_kernel(const float* __restrict__ pos,
                               const int* __restrict__ ei,
                               const int* __restrict__ ej, int E) {
    int e = blockIdx.x * blockDim.x + threadIdx.x;
    if (e >= E) return;
    int i = __ldg(ei + e), j = __ldg(ej + e);
    const float2* p2 = (const float2*)pos;
    float2 pi = __ldg(p2 + i);
    float2 pj = __ldg(p2 + j);
    float dx = pi.x - pj.x;
    float dy = pi.y - pj.y;
    dx = fminf(1.f, fmaxf(-1.f, dx));
    dy = fminf(1.f, fmaxf(-1.f, dy));
    float m = (i != j) ? 1.f : 0.f;
    float r = sqrtf(dx * dx + dy * dy + 1e-12f);
    float u = fminf(1.f, fmaxf(-1.f, 2.f * r - 1.f));
    float v = atan2f(dy, dx) * 0.318309886183790672f;   // 1/pi
    float su = (u + 1.f) * 3.5f;
    int   iu = min(6, (int)floorf(su));
    float tu = su - (float)iu;
    float sv = (v + 1.f) * 3.5f;
    int   iv = min(6, (int)floorf(sv));
    float tv = sv - (float)iv;
    float4 w = make_float4((1.f - tu) * (1.f - tv) * m,
                           (1.f - tu) * tv * m,
                           tu * (1.f - tv) * m,
                           tu * tv * m);
    int kb = iu * 8 + iv;
    int p = atomicAdd(&g_cursor[i], 1);
    g_sjk[p] = j | (kb << 20);
    g_sw[p] = w;
}

// ---------------- layer 0: moment accumulation ------------------------------
// M0[i, kb*4 + c] = sum_{e->i} w_tap(e) * x[j_e, c]; appended x[i] at 256..259
__global__ void mom0_kernel(const float* __restrict__ X) {
    __shared__ float M0s[8 * 256];
    int warp = threadIdx.x >> 5, lane = threadIdx.x & 31;
    int node = blockIdx.x * 8 + warp;
    float* M = M0s + warp * 256;
    #pragma unroll
    for (int r = 0; r < 8; r++) M[r * 32 + lane] = 0.f;
    __syncwarp();
    if (node < NN) {
        int e0 = g_rowp[node], e1 = g_rowp[node + 1];
        int t = lane >> 2, c = lane & 3;
        bool act = lane < 16;
        int kadd = (t & 1) + ((t >> 1) << 3);
        for (int e = e0; e < e1; e++) {
            int jk = __ldg(g_sjk + e);
            float4 w = __ldg(&g_sw[e]);
            int j = jk & 0xFFFFF;
            int kb = jk >> 20;
            float4 xv = __ldg((const float4*)X + j);
            if (act) {
                float wt = (t == 0) ? w.x : (t == 1) ? w.y : (t == 2) ? w.z : w.w;
                float xc = (c == 0) ? xv.x : (c == 1) ? xv.y : (c == 2) ? xv.z : xv.w;
                M[(kb + kadd) * 4 + c] += wt * xc;
            }
        }
        __syncwarp();
        __half* dst = g_m0 + (size_t)node * 320;
        #pragma unroll
        for (int r = 0; r < 4; r++) {
            int idx = r * 64 + 2 * lane;
            *(__half2*)(dst + idx) = __floats2half2_rn(M[idx], M[idx + 1]);
        }
        float4 xi = __ldg((const float4*)X + node);
        __half2 hv;
        if (lane == 0)      hv = __floats2half2_rn(xi.x, xi.y);
        else if (lane == 1) hv = __floats2half2_rn(xi.z, xi.w);
        else                hv = __floats2half2_rn(0.f, 0.f);
        *(__half2*)(dst + 256 + 2 * lane) = hv;
    }
}

// ---------------- layer 0 weight pack ---------------------------------------
// rows 0..255: (kb,c) -> cw0 into cols 32..63; rows 256..259: fw0 into cols 0..31
__global__ void pack0_kernel(const float* __restrict__ cw0,
                             const float* __restrict__ fw0,
                             const float* __restrict__ cb0,
                             const float* __restrict__ fb0) {
    int idx = blockIdx.x * blockDim.x + threadIdx.x;   // over 320*64
    if (idx >= 320 * 64) return;
    int row = idx >> 6;
    int co = idx & 63;
    float v = 0.f;
    if (row < 256) {
        int kb = row >> 2, c = row & 3;
        if (co >= 32) v = __ldg(cw0 + (size_t)(kb * 4 + c) * 32 + (co - 32));
    } else if (row < 260) {
        int c = row - 256;
        if (co < 32) v = __ldg(fw0 + (size_t)c * 32 + co);
    }
    g_wb0[row * 64 + co] = __float2half(v);
    if (idx < 64)
        g_bias0[idx] = (idx < 32) ? __ldg(fb0 + idx) : __ldg(cb0 + idx - 32);
}

// ---------------- layer 0 GEMM: ans0 = [M0|x] @ Wb0, bias, relu -> g_ah -----
#define GAST 72
__global__ void __launch_bounds__(256)
gemmA_kernel() {
    extern __shared__ __half smA[];
    __half* As = smA;                    // [128][GAST]
    __half* Bs = smA + 128 * GAST;       // [320][GAST]
    int m0 = blockIdx.x * 128;
    int tid = threadIdx.x;

    // stage B fully (320 x 64)
    #pragma unroll
    for (int it = 0; it < 10; it++) {
        int idx = tid + it * 256;        // 2560 uint4
        int row = idx >> 3;
        int c8 = idx & 7;
        uint4 v = __ldg((const uint4*)(g_wb0 + row * 64 + c8 * 8));
        *(uint4*)(Bs + row * GAST + c8 * 8) = v;
    }

    int warp = tid >> 5, lane = tid & 31;
    int wm = warp & 3, wn = warp >> 2;   // 4 x 2 warps; warp tile 32m x 32n
    uint32_t asB = (uint32_t)__cvta_generic_to_shared(As);
    uint32_t bsB = (uint32_t)__cvta_generic_to_shared(Bs);

    float c[2][4][4];
    #pragma unroll
    for (int mi = 0; mi < 2; mi++)
        #pragma unroll
        for (int ni = 0; ni < 4; ni++)
            #pragma unroll
            for (int p = 0; p < 4; p++) c[mi][ni][p] = 0.f;

    for (int kc = 0; kc < 5; kc++) {
        __syncthreads();
        #pragma unroll
        for (int it = 0; it < 4; it++) {
            int idx = tid + it * 256;    // 1024 uint4
            int row = idx >> 3;
            int c8 = idx & 7;
            uint4 v = make_uint4(0, 0, 0, 0);
            if (m0 + row < NN)
                v = __ldg((const uint4*)(g_m0 + (size_t)(m0 + row) * 320 + kc * 64 + c8 * 8));
            *(uint4*)(As + row * GAST + c8 * 8) = v;
        }
        __syncthreads();
        #pragma unroll
        for (int ks = 0; ks < 4; ks++) {
            int k0 = ks * 16;
            uint32_t a[2][4];
            #pragma unroll
            for (int mi = 0; mi < 2; mi++) {
                int row = wm * 32 + mi * 16 + (lane & 15);
                int col = k0 + ((lane >> 4) << 3);
                ldsm4(a[mi][0], a[mi][1], a[mi][2], a[mi][3],
                      asB + (row * GAST + col) * 2);
            }
            int brow = kc * 64 + k0 + (lane & 15);
            #pragma unroll
            for (int nq = 0; nq < 2; nq++) {
                int bcol = wn * 32 + nq * 16 + ((lane >> 4) << 3);
                uint32_t b0, b1, b2, b3;
                ldsm4t(b0, b1, b2, b3, bsB + (brow * GAST + bcol) * 2);
                #pragma unroll
                for (int mi = 0; mi < 2; mi++) {
                    mma16816(c[mi][nq * 2 + 0], a[mi], b0, b1);
                    mma16816(c[mi][nq * 2 + 1], a[mi], b2, b3);
                }
            }
        }
    }

    // epilogue: bias + relu -> g_ah (fp16)
    #pragma unroll
    for (int mi = 0; mi < 2; mi++) {
        #pragma unroll
        for (int ni = 0; ni < 4; ni++) {
            int row0 = m0 + wm * 32 + mi * 16 + (lane >> 2);
            int col = wn * 32 + ni * 8 + 2 * (lane & 3);
            float2 bv = *(const float2*)(g_bias0 + col);
            if (row0 < NN)
                *(__half2*)(g_ah + (size_t)row0 * 64 + col) = __floats2half2_rn(
                    fmaxf(c[mi][ni][0] + bv.x, 0.f), fmaxf(c[mi][ni][1] + bv.y, 0.f));
            int row1 = row0 + 8;
            if (row1 < NN)
                *(__half2*)(g_ah + (size_t)row1 * 64 + col) = __floats2half2_rn(
                    fmaxf(c[mi][ni][2] + bv.x, 0.f), fmaxf(c[mi][ni][3] + bv.y, 0.f));
        }
    }
}

// ---------------- weight pack (layers 1-3): g_wc[k, col] = fp16 Wcat --------
__global__ void pack_kernel(const float* __restrict__ CW,
                            const float* __restrict__ FW,
                            const float* __restrict__ cb,
                            const float* __restrict__ fb,
                            int ncols, int ncolsPad, int coutShift, int coutMask,
                            int biasN) {
    int idx = blockIdx.x * blockDim.x + threadIdx.x;   // over 64*ncolsPad
    if (idx >= 64 * ncolsPad) return;
    int k = idx / ncolsPad;
    int col = idx - k * ncolsPad;
    int cout = 1 << coutShift;
    int kcoutTot = 64 << coutShift;
    float w = 0.f;
    if (col < ncols) {
        if (col < kcoutTot) {
            int kk = col >> coutShift;
            int co = col & coutMask;
            w = __ldg(CW + (size_t)(kk * 64 + k) * cout + co);
        } else {
            w = __ldg(FW + (size_t)k * cout + (col - kcoutTot));
        }
    }
    g_wc[k * NPAD + col] = __float2half(w);
    if (idx < biasN) g_bias[idx] = __ldg(cb + idx) + __ldg(fb + idx);
}

// ---------------- main GEMM (tensor cores): Y = Ah @ Wcat -------------------
#define AST 72    // As row stride (halves)
#define BST 136   // Bs row stride (halves)
#define CST 136   // C staging row stride (halves)
#define SMEMB ((128 * AST + 64 * BST) * 2)   // 35840 B

__global__ void __launch_bounds__(256, 2)
gemm64_kernel(int ystride) {
    extern __shared__ __half sm[];
    __half* As = sm;                 // [128][AST]
    __half* Bs = sm + 128 * AST;     // [64][BST]
    int n0 = blockIdx.x * 128;
    int m0 = blockIdx.y * 128;
    int tid = threadIdx.x;

    #pragma unroll
    for (int it = 0; it < 4; it++) {
        int idx = tid + it * 256;
        int row = idx >> 3;
        int c8 = idx & 7;
        uint4 v = make_uint4(0, 0, 0, 0);
        if (m0 + row < NN)
            v = __ldg((const uint4*)(g_ah + (size_t)(m0 + row) * 64 + c8 * 8));
        *(uint4*)(As + row * AST + c8 * 8) = v;
    }
    #pragma unroll
    for (int it = 0; it < 4; it++) {
        int idx = tid + it * 256;
        int row = idx >> 4;
        int c8 = idx & 15;
        uint4 v = __ldg((const uint4*)(g_wc + row * NPAD + n0 + c8 * 8));
        *(uint4*)(Bs + row * BST + c8 * 8) = v;
    }
    __syncthreads();

    int warp = tid >> 5, lane = tid & 31;
    int wm = warp & 3;
    int wn = warp >> 2;
    uint32_t asBase = (uint32_t)__cvta_generic_to_shared(As);
    uint32_t bsBase = (uint32_t)__cvta_generic_to_shared(Bs);

    float c[2][8][4];
    #pragma unroll
    for (int mi = 0; mi < 2; mi++)
        #pragma unroll
        for (int ni = 0; ni < 8; ni++)
            #pragma unroll
            for (int p = 0; p < 4; p++) c[mi][ni][p] = 0.f;

    #pragma unroll
    for (int ks = 0; ks < 4; ks++) {
        int k0 = ks * 16;
        uint32_t a[2][4];
        #pragma unroll
        for (int mi = 0; mi < 2; mi++) {
            int row = wm * 32 + mi * 16 + (lane & 15);
            int col = k0 + ((lane >> 4) << 3);
            ldsm4(a[mi][0], a[mi][1], a[mi][2], a[mi][3],
                  asBase + (row * AST + col) * 2);
        }
        #pragma unroll
        for (int nq = 0; nq < 4; nq++) {
            int row = k0 + (lane & 15);
            int col = wn * 64 + nq * 16 + ((lane >> 4) << 3);
            uint32_t b0, b1, b2, b3;
            ldsm4t(b0, b1, b2, b3, bsBase + (row * BST + col) * 2);
            #pragma unroll
            for (int mi = 0; mi < 2; mi++) {
                mma16816(c[mi][nq * 2 + 0], a[mi], b0, b1);
                mma16816(c[mi][nq * 2 + 1], a[mi], b2, b3);
            }
        }
    }

    __syncthreads();
    __half* Cs = sm;                      // [128][CST]
    #pragma unroll
    for (int mi = 0; mi < 2; mi++) {
        #pragma unroll
        for (int ni = 0; ni < 8; ni++) {
            int r0 = wm * 32 + mi * 16 + (lane >> 2);
            int col = wn * 64 + ni * 8 + 2 * (lane & 3);
            *(__half2*)(Cs + r0 * CST + col) =
                __floats2half2_rn(c[mi][ni][0], c[mi][ni][1]);
            *(__half2*)(Cs + (r0 + 8) * CST + col) =
                __floats2half2_rn(c[mi][ni][2], c[mi][ni][3]);
        }
    }
    __syncthreads();
    #pragma unroll
    for (int p = 0; p < 4; p++) {
        int row = p * 32 + (tid >> 3);
        int gr = m0 + row;
        if (gr < NN) {
            int col = (tid & 7) * 16;
            uint4 v0 = *(const uint4*)(Cs + row * CST + col);
            uint4 v1 = *(const uint4*)(Cs + row * CST + col + 8);
            __half* dst = g_y + (size_t)gr * ystride + n0 + col;
            *(uint4*)(dst) = v0;
            *(uint4*)(dst + 8) = v1;
        }
    }
}

// ---------------- gather for 64-wide layers (half2, all 64 ch per warp) -----
template <bool RES, bool WF32>
__global__ void gather64_kernel(const float* __restrict__ resid,
                                float* __restrict__ outF) {
    int warpId = (blockIdx.x * blockDim.x + threadIdx.x) >> 5;
    int lane = threadIdx.x & 31;
    if (warpId >= NN) return;
    int i = warpId;
    int e0 = g_rowp[i], e1 = g_rowp[i + 1];
    float2 acc = make_float2(0.f, 0.f);
    int jk = 0; float4 w = make_float4(0.f, 0.f, 0.f, 0.f);
    if (e0 < e1) { jk = __ldg(g_sjk + e0); w = __ldg(&g_sw[e0]); }
    for (int e = e0; e < e1; e++) {
        int jkc = jk; float4 wc = w;
        if (e + 1 < e1) { jk = __ldg(g_sjk + e + 1); w = __ldg(&g_sw[e + 1]); }
        int j = jkc & 0xFFFFF;
        int kb = jkc >> 20;
        const __half2* r = (const __half2*)(g_y + (size_t)j * YS1 + kb * 64 + 2 * lane);
        float2 f0 = __half22float2(__ldg(r));
        float2 f1 = __half22float2(__ldg(r + 32));    // +64 halves
        float2 f2 = __half22float2(__ldg(r + 256));   // +512 halves
        float2 f3 = __half22float2(__ldg(r + 288));   // +576 halves
        acc.x += wc.x * f0.x + wc.y * f1.x + wc.z * f2.x + wc.w * f3.x;
        acc.y += wc.x * f0.y + wc.y * f1.y + wc.z * f2.y + wc.w * f3.y;
    }
    float2 s = __half22float2(*(const __half2*)(g_y + (size_t)i * YS1 + 4096 + 2 * lane));
    float2 bv = *(const float2*)(g_bias + 2 * lane);
    float2 o = make_float2(acc.x + s.x + bv.x, acc.y + s.y + bv.y);
    if (RES) {
        float2 rv = *(const float2*)(resid + (size_t)i * 64 + 2 * lane);
        o.x += rv.x; o.y += rv.y;
    }
    if (WF32)
        *(float2*)(outF + (size_t)i * 64 + 2 * lane) = o;
    *(__half2*)(g_ah + (size_t)i * 64 + 2 * lane) =
        __floats2half2_rn(fmaxf(o.x, 0.f), fmaxf(o.y, 0.f));
}

// ---------------- final gather (Cout = 2) + /128 ----------------------------
__global__ void gatherF_kernel(const float* __restrict__ cb3,
                               const float* __restrict__ fb3,
                               float* __restrict__ out) {
    int warpId = (blockIdx.x * blockDim.x + threadIdx.x) >> 5;
    int lane = threadIdx.x & 31;
    if (warpId >= NN) return;
    int i = warpId;
    int e0 = g_rowp[i], e1 = g_rowp[i + 1];
    float accx = 0.f, accy = 0.f;
    for (int e = e0 + lane; e < e1; e += 32) {
        int jk = __ldg(g_sjk + e);
        float4 w = __ldg(&g_sw[e]);
        int j = jk & 0xFFFFF;
        int kb = jk >> 20;
        const __half2* r = (const __half2*)(g_y + (size_t)j * YS3 + kb * 2);
        float2 f0 = __half22float2(__ldg(r));
        float2 f1 = __half22float2(__ldg(r + 1));
        float2 f2 = __half22float2(__ldg(r + 8));
        float2 f3 = __half22float2(__ldg(r + 9));
        accx += w.x * f0.x + w.y * f1.x + w.z * f2.x + w.w * f3.x;
        accy += w.x * f0.y + w.y * f1.y + w.z * f2.y + w.w * f3.y;
    }
    #pragma unroll
    for (int off = 16; off > 0; off >>= 1) {
        accx += __shfl_down_sync(0xFFFFFFFFu, accx, off);
        accy += __shfl_down_sync(0xFFFFFFFFu, accy, off);
    }
    if (lane == 0) {
        float2 ds = __half22float2(*(const __half2*)(g_y + (size_t)i * YS3 + 128));
        out[2 * i]     = (accx + ds.x + cb3[0] + fb3[0]) * (1.f / 128.f);
        out[2 * i + 1] = (accy + ds.y + cb3[1] + fb3[1]) * (1.f / 128.f);
    }
}

// ---------------- launch ----------------------------------------------------
extern "C" void kernel_launch(void* const* d_in, const int* in_sizes, int n_in,
                              void* d_out, int out_size) {
    const float* pos  = (const float*)d_in[0];
    const float* feat = (const float*)d_in[1];
    const int*   ei   = (const int*)d_in[2];
    const int*   ej   = (const int*)d_in[3];
    const float* cw0 = (const float*)d_in[4];
    const float* cb0 = (const float*)d_in[5];
    const float* fw0 = (const float*)d_in[6];
    const float* fb0 = (const float*)d_in[7];
    const float* cw1 = (const float*)d_in[8];
    const float* cb1 = (const float*)d_in[9];
    const float* fw1 = (const float*)d_in[10];
    const float* fb1 = (const float*)d_in[11];
    const float* cw2 = (const float*)d_in[12];
    const float* cb2 = (const float*)d_in[13];
    const float* fw2 = (const float*)d_in[14];
    const float* fb2 = (const float*)d_in[15];
    const float* cw3 = (const float*)d_in[16];
    const float* cb3 = (const float*)d_in[17];
    const float* fw3 = (const float*)d_in[18];
    const float* fb3 = (const float*)d_in[19];
    float* out = (float*)d_out;
    int E = in_sizes[2];

    cudaFuncSetAttribute(gemm64_kernel,
                         cudaFuncAttributeMaxDynamicSharedMemorySize, SMEMB);
    const int SMEMA = (128 * GAST + 320 * GAST) * 2;   // 64512 B
    cudaFuncSetAttribute(gemmA_kernel,
                         cudaFuncAttributeMaxDynamicSharedMemorySize, SMEMA);

    float* aF; cudaGetSymbolAddress((void**)&aF, g_ansF);

    // edge counting sort
    zero_cnt_kernel<<<(NN + 256) / 256, 256>>>();
    hist_kernel<<<(E + 255) / 256, 256>>>(ei, E);
    scan1_kernel<<<SCAN_B, 1024>>>();
    scan2_kernel<<<1, 64>>>();
    scan3_kernel<<<SCAN_B, 1024>>>();
    scatter_kernel<<<(E + 255) / 256, 256>>>(pos, ei, ej, E);

    // layer 0 (moment formulation)
    pack0_kernel<<<(320 * 64 + 255) / 256, 256>>>(cw0, fw0, cb0, fb0);
    mom0_kernel<<<NN / 8, 256>>>(feat);
    gemmA_kernel<<<391, 256, SMEMA>>>();

    // layer 1
    pack_kernel<<<(64 * NPAD + 255) / 256, 256>>>(cw1, fw1, cb1, fb1, 4160, NPAD, 6, 63, 64);
    gemm64_kernel<<<dim3(33, 391), 256, SMEMB>>>(YS1);
    gather64_kernel<false, true><<<(NN * 32 + 255) / 256, 256>>>(nullptr, aF);

    // layer 2 (residual = ansF)
    pack_kernel<<<(64 * NPAD + 255) / 256, 256>>>(cw2, fw2, cb2, fb2, 4160, NPAD, 6, 63, 64);
    gemm64_kernel<<<dim3(33, 391), 256, SMEMB>>>(YS1);
    gather64_kernel<true, false><<<(NN * 32 + 255) / 256, 256>>>(aF, nullptr);

    // layer 3
    pack_kernel<<<(64 * 256 + 255) / 256, 256>>>(cw3, fw3, cb3, fb3, 130, 256, 1, 1, 0);
    gemm64_kernel<<<dim3(2, 391), 256, SMEMB>>>(YS3);
    gatherF_kernel<<<(NN * 32 + 255) / 256, 256>>>(cb3, fb3, out);
}